// round 15
// baseline (speedup 1.0000x reference)
#include <cuda_runtime.h>
#include <cuda_bf16.h>
#include <cstdint>

// LSTM B=4096,T=512,IN=1,H=32,OUT=1 — bf16 m16n8k16 mma.sync, fp32 accum/cell.
// R15: 8-warp CTAs (256 thr), NB=8, grid=512 -> 4096 warps (~7/SMSP, 2x R11).
// Warp w owns ONE m-tile: permuted rows = all 4 gates for hidden [4w,4w+4).
// Thread has gates {i,g} or {f,o}; lane pair l <-> l^16 swaps the missing two
// via 2x shfl.xor -> epilogue (1 cell/thread) stays register-local.
// One bar.sync(256) per step; h as bf16x2 in smem (layout = R11, verified).

#define TT  512
#define HH  32
#define BB  4096
#define NB  8

typedef unsigned long long u64;

__device__ __forceinline__ uint32_t pack_bf16(float lo, float hi) {
    uint32_t r;                        // first asm src -> upper half
    asm("cvt.rn.bf16x2.f32 %0, %1, %2;" : "=r"(r) : "f"(hi), "f"(lo));
    return r;
}
__device__ __forceinline__ float tanh_hw(float x) {
    float r;
    asm("tanh.approx.f32 %0, %1;" : "=f"(r) : "f"(x));
    return r;
}
__device__ __forceinline__ void mma_bf16(float* d, const uint32_t* a,
                                         const uint32_t* b) {
    asm volatile(
        "mma.sync.aligned.m16n8k16.row.col.f32.bf16.bf16.f32 "
        "{%0,%1,%2,%3}, {%4,%5,%6,%7}, {%8,%9}, {%0,%1,%2,%3};"
        : "+f"(d[0]), "+f"(d[1]), "+f"(d[2]), "+f"(d[3])
        : "r"(a[0]), "r"(a[1]), "r"(a[2]), "r"(a[3]), "r"(b[0]), "r"(b[1]));
}

// h layout (R11-verified): 128 u32 words of bf16x2 per buffer.
// word(n, kp=k>>1) = (k>>4)*64 + ((k>>1)&3)*16 + n*2 + ((k>>3)&1).
// B-fragment (kt): LDS.64 at word kt*64 + lq*16 + gid*2.

__global__ __launch_bounds__(256, 4)
void lstm_w8_kernel(const float* __restrict__ x,      // [B,T]
                    const float* __restrict__ W_ih,   // [4H]
                    const float* __restrict__ W_hh,   // [4H,H]
                    const float* __restrict__ b_ih,   // [4H]
                    const float* __restrict__ b_hh,   // [4H]
                    const float* __restrict__ fc_w,   // [H]
                    const float* __restrict__ fc_b,   // [1]
                    float* __restrict__ out)          // [B]
{
    __shared__ __align__(16) uint32_t hbuf[2][128];   // bf16x2, permuted
    __shared__ __align__(16) float    xs[64][NB];     // x chunk [t][n]

    const int tid  = threadIdx.x;
    const int w    = tid >> 5;          // 0..7 : m-tile / hidden block [4w,4w+4)
    const int l    = tid & 31;
    const int gid  = l >> 2;            // 0..7
    const int lq   = l & 3;             // 0..3
    const int side = gid >> 2;          // 0: gates {i,g}; 1: gates {f,o}
    const int j    = 4 * w + (gid & 3); // hidden unit owned
    const int n    = 2 * lq + side;     // batch column this thread epilogues
    const int b0   = blockIdx.x * NB;

    // Permuted A rows: tile row gid -> gate side (i or f), row gid+8 -> side+2.
    const int rA = side * HH + j;          // gate i or f (sigmoid: x0.5)
    const int rB = (side + 2) * HH + j;    // gate g (x1) or o (x0.5)
    const float sA = 0.5f;
    const float sB = side ? 0.5f : 1.0f;
    const float* pA = W_hh + rA * HH;
    const float* pB = W_hh + rB * HH;

    uint32_t af[2][4];
    #pragma unroll
    for (int kt = 0; kt < 2; kt++) {
        const int k0 = kt * 16 + 2 * lq;
        af[kt][0] = pack_bf16(pA[k0] * sA,     pA[k0 + 1] * sA);
        af[kt][1] = pack_bf16(pB[k0] * sB,     pB[k0 + 1] * sB);
        af[kt][2] = pack_bf16(pA[k0 + 8] * sA, pA[k0 + 9] * sA);
        af[kt][3] = pack_bf16(pB[k0 + 8] * sB, pB[k0 + 9] * sB);
    }
    const float wihA  = W_ih[rA] * sA;
    const float biasA = (b_ih[rA] + b_hh[rA]) * sA;
    const float wihB  = W_ih[rB] * sB;
    const float biasB = (b_ih[rB] + b_hh[rB]) * sB;

    if (tid < 128) hbuf[0][tid] = 0u;   // h_0 = 0

    // Hoisted addresses
    const uint32_t* bfp[2] = { &hbuf[0][lq * 16 + gid * 2],
                               &hbuf[1][lq * 16 + gid * 2] };
    const int stw = (j >> 4) * 64 + ((j >> 1) & 3) * 16 + n * 2 + ((j >> 3) & 1);
    uint16_t* stp[2] = {
        reinterpret_cast<uint16_t*>(&hbuf[0][stw]) + (j & 1),
        reinterpret_cast<uint16_t*>(&hbuf[1][stw]) + (j & 1) };

    float c = 0.0f;

    #pragma unroll 1
    for (int tb = 0; tb < TT; tb += 2) {
        if ((tb & 63) == 0) {
            // refill x chunk [tb, tb+64): coalesced (t_ = tid&31 contiguous)
            const int nn = tid >> 5, t0 = tid & 31;
            const float* src = x + (size_t)(b0 + nn) * TT + tb + t0;
            xs[t0][nn]      = src[0];
            xs[t0 + 32][nn] = src[32];
            __syncthreads();
        }

        #pragma unroll
        for (int ph = 0; ph < 2; ph++) {
            const int t = tb + ph;
            const int p = ph;                  // tb even -> parity == ph

            // acc init (covers both cols n0=2lq, n1=2lq+1)
            const float2 xv = *reinterpret_cast<const float2*>(&xs[t & 63][2 * lq]);
            float acc[4];
            acc[0] = fmaf(xv.x, wihA, biasA);
            acc[1] = fmaf(xv.y, wihA, biasA);
            acc[2] = fmaf(xv.x, wihB, biasB);
            acc[3] = fmaf(xv.y, wihB, biasB);

            // B fragments (2 conflict-free LDS.64)
            uint32_t bf0[2], bf1[2];
            {
                const u64 v0 = *reinterpret_cast<const u64*>(bfp[p]);
                const u64 v1 = *reinterpret_cast<const u64*>(bfp[p] + 64);
                bf0[0] = (uint32_t)v0; bf0[1] = (uint32_t)(v0 >> 32);
                bf1[0] = (uint32_t)v1; bf1[1] = (uint32_t)(v1 >> 32);
            }

            // one m-tile, K=32: chain of 2 HMMAs
            mma_bf16(acc, af[0], bf0);
            mma_bf16(acc, af[1], bf1);

            // gate exchange with lane l^16:
            // side0 keeps col n0 (acc0=i(n0), acc2=g(n0)), sends i(n1),g(n1)
            // side1 keeps col n1 (acc1=f(n1), acc3=o(n1)), sends f(n0),o(n0)
            const float s1 = side ? acc[0] : acc[1];
            const float r1 = __shfl_xor_sync(0xffffffffu, s1, 16);
            const float s2 = side ? acc[2] : acc[3];
            const float r2 = __shfl_xor_sync(0xffffffffu, s2, 16);

            const float pi = side ? r1     : acc[0];
            const float pf = side ? acc[1] : r1;
            const float pg = side ? r2     : acc[2];
            const float po = side ? acc[3] : r2;

            // epilogue: 1 cell (j, n)
            const float gi = fmaf(0.5f, tanh_hw(pi), 0.5f);
            const float gf = fmaf(0.5f, tanh_hw(pf), 0.5f);
            const float gg =             tanh_hw(pg);
            const float go = fmaf(0.5f, tanh_hw(po), 0.5f);
            c = fmaf(gf, c, gi * gg);
            const float h = go * tanh_hw(c);
            __nv_bfloat16 hb = __float2bfloat16(h);
            stp[p ^ 1][0] = *reinterpret_cast<uint16_t*>(&hb);

            __syncthreads();
        }
    }

    // out[n] = dot(h[n,:], fc_w) + fc_b   (final h in hbuf[0]: T even)
    if (tid < NB) {
        const int nn = tid;
        const uint16_t* hb16 = reinterpret_cast<const uint16_t*>(hbuf[0]);
        float s = fc_b[0];
        #pragma unroll
        for (int k = 0; k < HH; k++) {
            const int word = (k >> 4) * 64 + ((k >> 1) & 3) * 16 + nn * 2 + ((k >> 3) & 1);
            const uint16_t bits = hb16[word * 2 + (k & 1)];
            __nv_bfloat16 hv = *reinterpret_cast<const __nv_bfloat16*>(&bits);
            s = fmaf(__bfloat162float(hv), fc_w[k], s);
        }
        out[b0 + nn] = s;
    }
}

extern "C" void kernel_launch(void* const* d_in, const int* in_sizes, int n_in,
                              void* d_out, int out_size) {
    const float* x    = (const float*)d_in[0];
    const float* W_ih = (const float*)d_in[1];
    const float* W_hh = (const float*)d_in[2];
    const float* b_ih = (const float*)d_in[3];
    const float* b_hh = (const float*)d_in[4];
    const float* fc_w = (const float*)d_in[5];
    const float* fc_b = (const float*)d_in[6];
    float* out = (float*)d_out;

    lstm_w8_kernel<<<BB / NB, 256>>>(x, W_ih, W_hh, b_ih, b_hh, fc_w, fc_b, out);
}

// round 16
// speedup vs baseline: 1.2918x; 1.2918x over previous
#include <cuda_runtime.h>
#include <cuda_bf16.h>
#include <cstdint>

// LSTM B=4096,T=512,IN=1,H=32,OUT=1 — bf16 m16n8k16 mma.sync, fp32 accum/cell.
// R16 = R11 (best: 139.3us) + three critical-chain cuts:
//  1) K=32 as two PARALLEL HMMAs + FADD merge (no depth-2 tensor chain)
//  2) next step's acc-init (x*W_ih+bias) hoisted ABOVE the barrier
//  3) all 512 x-values per element preloaded to smem once (no refill barriers)
// Layout identical to R11: 512 CTAs x 128 thr, NB=8, warp w owns hidden
// [8w,8w+8) of all 4 gates, h as bf16x2 in permuted smem, 1 bar.sync/step.

#define TT  512
#define HH  32
#define BB  4096
#define NB  8

typedef unsigned long long u64;

__device__ __forceinline__ uint32_t pack_bf16(float lo, float hi) {
    uint32_t r;                        // first asm src -> upper half
    asm("cvt.rn.bf16x2.f32 %0, %1, %2;" : "=r"(r) : "f"(hi), "f"(lo));
    return r;
}
__device__ __forceinline__ float tanh_hw(float x) {
    float r;
    asm("tanh.approx.f32 %0, %1;" : "=f"(r) : "f"(x));
    return r;
}
__device__ __forceinline__ void mma_bf16(float* d, const uint32_t* a,
                                         const uint32_t* b) {
    asm volatile(
        "mma.sync.aligned.m16n8k16.row.col.f32.bf16.bf16.f32 "
        "{%0,%1,%2,%3}, {%4,%5,%6,%7}, {%8,%9}, {%0,%1,%2,%3};"
        : "+f"(d[0]), "+f"(d[1]), "+f"(d[2]), "+f"(d[3])
        : "r"(a[0]), "r"(a[1]), "r"(a[2]), "r"(a[3]), "r"(b[0]), "r"(b[1]));
}

// h layout (R11-verified): 128 u32 words of bf16x2 per buffer.
// word(n, kp=k>>1) = (k>>4)*64 + ((k>>1)&3)*16 + n*2 + ((k>>3)&1).
// B-fragment (kt): LDS.64 at word kt*64 + lq*16 + gid*2.

__global__ __launch_bounds__(128, 4)
void lstm_r16_kernel(const float* __restrict__ x,      // [B,T]
                     const float* __restrict__ W_ih,   // [4H]
                     const float* __restrict__ W_hh,   // [4H,H]
                     const float* __restrict__ b_ih,   // [4H]
                     const float* __restrict__ b_hh,   // [4H]
                     const float* __restrict__ fc_w,   // [H]
                     const float* __restrict__ fc_b,   // [1]
                     float* __restrict__ out)          // [B]
{
    __shared__ __align__(16) uint32_t hbuf[2][128];   // bf16x2, permuted
    __shared__ __align__(16) float    xs[TT + 2][NB]; // ALL x, padded tail

    const int tid = threadIdx.x;
    const int w   = tid >> 5;
    const int l   = tid & 31;
    const int gid = l >> 2;            // 0..7
    const int lq  = l & 3;             // 0..3
    const int b0  = blockIdx.x * NB;
    const int j   = 8 * w + gid;       // hidden unit owned in epilogue

    // Preload ALL x for this CTA's 8 elements (one-time, coalesced):
    // thread handles elem n = tid>>4, slice s = tid&15 (32 consecutive floats).
    {
        const int n = tid >> 4, s = tid & 15;
        const float4* src =
            reinterpret_cast<const float4*>(x + (size_t)(b0 + n) * TT) + s * 8;
        #pragma unroll
        for (int i = 0; i < 8; i++) {
            const float4 v = src[i];
            const int t0 = s * 32 + i * 4;
            xs[t0 + 0][n] = v.x;
            xs[t0 + 1][n] = v.y;
            xs[t0 + 2][n] = v.z;
            xs[t0 + 3][n] = v.w;
        }
        if (tid < 2 * NB) xs[TT + (tid >> 3)][tid & 7] = 0.0f;  // pad rows
    }

    // A fragments (persistent, bf16); sigmoid gates (0,1,3) pre-scaled x0.5.
    uint32_t af[2][2][4];
    #pragma unroll
    for (int mt = 0; mt < 2; mt++) {
        const int g0 = 2 * mt, g1 = 2 * mt + 1;
        const float s0 = (g0 == 2) ? 1.0f : 0.5f;
        const float s1 = (g1 == 2) ? 1.0f : 0.5f;
        const float* r0 = W_hh + (g0 * HH + j) * HH;
        const float* r1 = W_hh + (g1 * HH + j) * HH;
        #pragma unroll
        for (int kt = 0; kt < 2; kt++) {
            const int k0 = kt * 16 + 2 * lq;
            af[mt][kt][0] = pack_bf16(r0[k0] * s0,     r0[k0 + 1] * s0);
            af[mt][kt][1] = pack_bf16(r1[k0] * s1,     r1[k0 + 1] * s1);
            af[mt][kt][2] = pack_bf16(r0[k0 + 8] * s0, r0[k0 + 9] * s0);
            af[mt][kt][3] = pack_bf16(r1[k0 + 8] * s1, r1[k0 + 9] * s1);
        }
    }

    float wih[4], bias[4];
    #pragma unroll
    for (int g = 0; g < 4; g++) {
        const float sc = (g == 2) ? 1.0f : 0.5f;
        wih[g]  = W_ih[g * HH + j] * sc;
        bias[g] = (b_ih[g * HH + j] + b_hh[g * HH + j]) * sc;
    }

    if (tid < 128) hbuf[0][tid] = 0u;   // h_0 = 0

    // Hoisted addresses
    const uint32_t* bfp[2] = { &hbuf[0][lq * 16 + gid * 2],
                               &hbuf[1][lq * 16 + gid * 2] };
    const int stw = (j >> 4) * 64 + ((j >> 1) & 3) * 16 + (2 * lq) * 2 + ((j >> 3) & 1);
    const int sth = (j & 1);
    uint16_t* stp[2] = {
        reinterpret_cast<uint16_t*>(&hbuf[0][stw]) + sth,
        reinterpret_cast<uint16_t*>(&hbuf[1][stw]) + sth };

    float c0 = 0.0f, c1 = 0.0f;

    // acc-init for step 0 (hoisted pattern: accI always holds NEXT step's init)
    float accI[2][4];
    {
        const float2 xv = *reinterpret_cast<const float2*>(&xs[0][2 * lq]);
        #pragma unroll
        for (int mt = 0; mt < 2; mt++) {
            accI[mt][0] = fmaf(xv.x, wih[2 * mt],     bias[2 * mt]);
            accI[mt][1] = fmaf(xv.y, wih[2 * mt],     bias[2 * mt]);
            accI[mt][2] = fmaf(xv.x, wih[2 * mt + 1], bias[2 * mt + 1]);
            accI[mt][3] = fmaf(xv.y, wih[2 * mt + 1], bias[2 * mt + 1]);
        }
    }

    __syncthreads();   // x, h_0 visible

    #pragma unroll 1
    for (int tb = 0; tb < TT; tb += 2) {
        #pragma unroll
        for (int ph = 0; ph < 2; ph++) {
            const int t = tb + ph;
            const int p = ph;                  // tb even -> parity == ph

            // B fragments (2 conflict-free LDS.64) — the only post-bar dep
            uint32_t bf[2][2];
            #pragma unroll
            for (int kt = 0; kt < 2; kt++) {
                const u64 v = *reinterpret_cast<const u64*>(bfp[p] + kt * 64);
                bf[kt][0] = (uint32_t)v;
                bf[kt][1] = (uint32_t)(v >> 32);
            }

            // Two PARALLEL HMMAs per gate-pair (no chain), FADD merge
            float accQ[2][4] = {{0.f, 0.f, 0.f, 0.f}, {0.f, 0.f, 0.f, 0.f}};
            #pragma unroll
            for (int mt = 0; mt < 2; mt++) {
                mma_bf16(accI[mt], af[mt][0], bf[0]);
                mma_bf16(accQ[mt], af[mt][1], bf[1]);
            }
            float acc[2][4];
            #pragma unroll
            for (int mt = 0; mt < 2; mt++)
                #pragma unroll
                for (int q = 0; q < 4; q++)
                    acc[mt][q] = accI[mt][q] + accQ[mt][q];

            // epilogue: 2 register-local cells (n = 2lq, 2lq+1; hidden j)
            {
                const float gi0 = fmaf(0.5f, tanh_hw(acc[0][0]), 0.5f);
                const float gi1 = fmaf(0.5f, tanh_hw(acc[0][1]), 0.5f);
                const float gf0 = fmaf(0.5f, tanh_hw(acc[0][2]), 0.5f);
                const float gf1 = fmaf(0.5f, tanh_hw(acc[0][3]), 0.5f);
                const float gg0 =             tanh_hw(acc[1][0]);
                const float gg1 =             tanh_hw(acc[1][1]);
                const float go0 = fmaf(0.5f, tanh_hw(acc[1][2]), 0.5f);
                const float go1 = fmaf(0.5f, tanh_hw(acc[1][3]), 0.5f);
                c0 = fmaf(gf0, c0, gi0 * gg0);
                c1 = fmaf(gf1, c1, gi1 * gg1);
                const float h0 = go0 * tanh_hw(c0);
                const float h1 = go1 * tanh_hw(c1);
                __nv_bfloat16 hb0 = __float2bfloat16(h0);
                __nv_bfloat16 hb1 = __float2bfloat16(h1);
                stp[p ^ 1][0] = *reinterpret_cast<uint16_t*>(&hb0);
                stp[p ^ 1][4] = *reinterpret_cast<uint16_t*>(&hb1);
            }

            // HOISTED: next step's acc-init (xs immutable -> legal pre-bar)
            {
                const float2 xn =
                    *reinterpret_cast<const float2*>(&xs[t + 1][2 * lq]);
                #pragma unroll
                for (int mt = 0; mt < 2; mt++) {
                    accI[mt][0] = fmaf(xn.x, wih[2 * mt],     bias[2 * mt]);
                    accI[mt][1] = fmaf(xn.y, wih[2 * mt],     bias[2 * mt]);
                    accI[mt][2] = fmaf(xn.x, wih[2 * mt + 1], bias[2 * mt + 1]);
                    accI[mt][3] = fmaf(xn.y, wih[2 * mt + 1], bias[2 * mt + 1]);
                }
            }

            __syncthreads();
        }
    }

    // out[n] = dot(h[n,:], fc_w) + fc_b   (final h in hbuf[0]: T even)
    if (tid < NB) {
        const int n = tid;
        const uint16_t* hb16 = reinterpret_cast<const uint16_t*>(hbuf[0]);
        float s = fc_b[0];
        #pragma unroll
        for (int k = 0; k < HH; k++) {
            const int word = (k >> 4) * 64 + ((k >> 1) & 3) * 16 + n * 2 + ((k >> 3) & 1);
            const uint16_t bits = hb16[word * 2 + (k & 1)];
            __nv_bfloat16 hv = *reinterpret_cast<const __nv_bfloat16*>(&bits);
            s = fmaf(__bfloat162float(hv), fc_w[k], s);
        }
        out[b0 + n] = s;
    }
}

extern "C" void kernel_launch(void* const* d_in, const int* in_sizes, int n_in,
                              void* d_out, int out_size) {
    const float* x    = (const float*)d_in[0];
    const float* W_ih = (const float*)d_in[1];
    const float* W_hh = (const float*)d_in[2];
    const float* b_ih = (const float*)d_in[3];
    const float* b_hh = (const float*)d_in[4];
    const float* fc_w = (const float*)d_in[5];
    const float* fc_b = (const float*)d_in[6];
    float* out = (float*)d_out;

    lstm_r16_kernel<<<BB / NB, 128>>>(x, W_ih, W_hh, b_ih, b_hh, fc_w, fc_b, out);
}